// round 2
// baseline (speedup 1.0000x reference)
#include <cuda_runtime.h>
#include <cuda_fp16.h>
#include <cstdint>
#include <cstddef>

#define BATCH   32
#define NVARS   16
#define SAMPLES 4096
#define EMB     128
#define SPAD    4128      // padded sample rows (max needed s = 4123)
#define NTOK    1016
#define NIT     64        // 2 passes (W_hi, W_lo) * 32 window positions

// Scratch (device globals: allocation-free rule)
__device__ __align__(1024) __half g_enc[(size_t)BATCH * SPAD * EMB];   // ~33.8 MB
__device__ __align__(1024) __half g_wt[2ull * 128 * 4096];             // Wt[pass][n][k], 2 MB

// ======================= helpers =======================
__device__ __forceinline__ uint32_t smem_u32(const void* p) {
    uint32_t a;
    asm("{ .reg .u64 t; cvta.to.shared.u64 t, %1; cvt.u32.u64 %0, t; }" : "=r"(a) : "l"(p));
    return a;
}
#define CP16(dst, src) \
    asm volatile("cp.async.cg.shared.global [%0], [%1], 16;" :: "r"(dst), "l"(src))
#define CP_COMMIT()  asm volatile("cp.async.commit_group;" ::: "memory")
#define CP_WAIT(n)   asm volatile("cp.async.wait_group %0;" :: "n"(n) : "memory")

#define LDSM4(r, addr) \
    asm volatile("ldmatrix.sync.aligned.m8n8.x4.shared.b16 {%0,%1,%2,%3}, [%4];" \
        : "=r"((r)[0]), "=r"((r)[1]), "=r"((r)[2]), "=r"((r)[3]) : "r"(addr))

#define MMA16816(d, a, b0, b1) \
    asm volatile("mma.sync.aligned.m16n8k16.row.col.f32.f16.f16.f32 " \
        "{%0,%1,%2,%3}, {%4,%5,%6,%7}, {%8,%9}, {%0,%1,%2,%3};" \
        : "+f"((d)[0]), "+f"((d)[1]), "+f"((d)[2]), "+f"((d)[3]) \
        : "r"((a)[0]), "r"((a)[1]), "r"((a)[2]), "r"((a)[3]), "r"(b0), "r"(b1))

// ======================= Kernel 1: split+transpose W_patch =======================
// Wt[pass][n][k] : pass 0 = fp16(W), pass 1 = fp16(W - hi). Two-term split, residual ~2^-22.
__global__ void prep_w_kernel(const float* __restrict__ Wp) {
    int idx = blockIdx.x * 128 + threadIdx.x;      // 524288 elements, grid 4096
    float w = Wp[idx];
    int k = idx >> 7, n = idx & 127;
    __half hi = __float2half_rn(w);
    float lo = w - __half2float(hi);
    g_wt[(size_t)n * 4096 + k]          = hi;
    g_wt[524288 + (size_t)n * 4096 + k] = __float2half_rn(lo);
}

// ======================= Kernel 2: encode (stage-1 LSH) =======================
// enc[b,s,d] = floor(sum_v x[b,v,s]*Ws[v,d] + bs[d]); |enc| < ~48 -> exact in fp16.
// Pad rows [4096,4128) with 0.
__global__ void encode_kernel(const float* __restrict__ x,
                              const float* __restrict__ Ws,
                              const float* __restrict__ bs) {
    int b = blockIdx.y;
    int s0 = blockIdx.x * 8;
    int tid = threadIdx.x;   // 128 threads; tid == embed dim d
    __shared__ float xs[NVARS][8];
    {
        int v = tid >> 3, s = tid & 7;
        int sg = s0 + s;
        xs[v][s] = (sg < SAMPLES) ? x[((size_t)b * NVARS + v) * SAMPLES + sg] : 0.f;
    }
    __syncthreads();
    float wv[NVARS];
#pragma unroll
    for (int v = 0; v < NVARS; v++) wv[v] = Ws[v * EMB + tid];
    float bias = bs[tid];
#pragma unroll
    for (int s = 0; s < 8; s++) {
        int sg = s0 + s;
        float acc = bias;
#pragma unroll
        for (int v = 0; v < NVARS; v++) acc += xs[v][s] * wv[v];
        float val = (sg < SAMPLES) ? floorf(acc) : 0.f;
        g_enc[((size_t)b * SPAD + sg) * EMB + tid] = __float2half_rn(val);
    }
}

// ======================= Kernel 3: windowed GEMM (mma.sync fp16) =======================
// Per CTA: 128-token M-tile of one batch, N=128, K = 2 passes * 32 window pos * 128 dim.
// A[m, w*128+d] = enc[b, (t0+m)*4+w, d]  (no materialization; strided loads per w)
// B[n, ...]     = Wt[pass][n][w*128+d]
// out[b,t,n] = floor(D + b_patch[n])
//
// SMEM: [512,1024) bias fp32 | two 64KB buffers: A tile 32KB + B tile 32KB each.
// Tiles stored row-major, 256B/row, 16B-chunk XOR swizzle: chunk' = chunk ^ (row&7).
#define SM_A(buf) (1024u + (buf) * 65536u)
#define SM_B(buf) (1024u + (buf) * 65536u + 32768u)
#define SMEM_BYTES (1024 + 2 * 65536)

__global__ void __launch_bounds__(256, 1)
gemm_kernel(const float* __restrict__ bp, float* __restrict__ out) {
    extern __shared__ char smem[];
    uint32_t sb = smem_u32(smem);
    int tid = threadIdx.x, wid = tid >> 5, lid = tid & 31;
    int t0 = blockIdx.x * 128;
    int b  = blockIdx.y;

    if (tid < 128) ((float*)(smem + 512))[tid] = bp[tid];

    float acc[2][8][4];
#pragma unroll
    for (int i = 0; i < 2; i++)
#pragma unroll
        for (int j = 0; j < 8; j++)
#pragma unroll
            for (int k = 0; k < 4; k++) acc[i][j][k] = 0.f;

    const __half* aG = g_enc + ((size_t)b * SPAD + (size_t)t0 * 4) * EMB;

    // ---- producer: fill one 64KB buffer (A+B) with cp.async ----
    auto fill = [&](int it, int buf) {
        int pass = it >> 5, w = it & 31;
        const __half* aBase = aG + (size_t)w * EMB;
        const __half* bBase = g_wt + (size_t)pass * 524288 + (size_t)w * EMB;
#pragma unroll
        for (int r = 0; r < 8; r++) {
            int g = tid + r * 256;          // chunk id 0..2047
            int row = g >> 4, c = g & 15;   // row in tile, 16B chunk in row
            uint32_t off = (uint32_t)row * 256 + (uint32_t)((c ^ (row & 7)) << 4);
            CP16(sb + SM_A(buf) + off, (const void*)(aBase + (size_t)row * 512 + c * 8));
            CP16(sb + SM_B(buf) + off, (const void*)(bBase + (size_t)row * 4096 + c * 8));
        }
        CP_COMMIT();
    };

    // ---- consumer addressing (warp tile 32m x 64n; warp grid 4x2) ----
    int wr = wid & 3, wc = wid >> 2;
    uint32_t xorv = (uint32_t)(lid & 7);
    uint32_t aRowOff[2], bRowOff[4];
#pragma unroll
    for (int t = 0; t < 2; t++)
        aRowOff[t] = (uint32_t)(wr * 32 + t * 16 + (lid & 15)) * 256;
#pragma unroll
    for (int p = 0; p < 4; p++)
        bRowOff[p] = (uint32_t)(wc * 64 + p * 16 + (lid & 7) + ((lid & 16) ? 8 : 0)) * 256;
    uint32_t cbA = (uint32_t)(lid >> 4);        // k-half select for A ldmatrix
    uint32_t cbB = (uint32_t)((lid >> 3) & 1);  // k-half select for B ldmatrix

    auto compute = [&](int buf) {
        uint32_t baseA = sb + SM_A(buf), baseB = sb + SM_B(buf);
#pragma unroll
        for (int kk = 0; kk < 8; kk++) {
            uint32_t afr[2][4];
#pragma unroll
            for (int mi = 0; mi < 2; mi++)
                LDSM4(afr[mi], baseA + aRowOff[mi] + (((2u * kk + cbA) ^ xorv) << 4));
            uint32_t bfr[4][4];
#pragma unroll
            for (int p = 0; p < 4; p++)
                LDSM4(bfr[p], baseB + bRowOff[p] + (((2u * kk + cbB) ^ xorv) << 4));
#pragma unroll
            for (int mi = 0; mi < 2; mi++)
#pragma unroll
                for (int p = 0; p < 4; p++) {
                    MMA16816(acc[mi][2 * p],     afr[mi], bfr[p][0], bfr[p][1]);
                    MMA16816(acc[mi][2 * p + 1], afr[mi], bfr[p][2], bfr[p][3]);
                }
        }
    };

    // ---- double-buffered main loop ----
    fill(0, 0);
    for (int it = 0; it < NIT; it++) {
        int buf = it & 1;
        if (it + 1 < NIT) {
            fill(it + 1, buf ^ 1);
            CP_WAIT(1);            // fill(it) complete
        } else {
            CP_WAIT(0);
        }
        __syncthreads();
        compute(buf);
        __syncthreads();           // buffer reuse guard for fill(it+2)
    }

    // ---- epilogue: D + b_patch, floor, fp32 stores ----
    const float* bsm = (const float*)(smem + 512);
    int rbase = wr * 32 + (lid >> 2);
    int nb = wc * 64 + (lid & 3) * 2;
#pragma unroll
    for (int mi = 0; mi < 2; mi++) {
        int trow0 = t0 + rbase + mi * 16;
#pragma unroll
        for (int ni = 0; ni < 8; ni++) {
            int n = nb + ni * 8;
            float bx = bsm[n], by = bsm[n + 1];
            if (trow0 < NTOK) {
                float2 v;
                v.x = floorf(acc[mi][ni][0] + bx);
                v.y = floorf(acc[mi][ni][1] + by);
                *(float2*)(out + ((size_t)b * NTOK + trow0) * 128 + n) = v;
            }
            if (trow0 + 8 < NTOK) {
                float2 v;
                v.x = floorf(acc[mi][ni][2] + bx);
                v.y = floorf(acc[mi][ni][3] + by);
                *(float2*)(out + ((size_t)b * NTOK + trow0 + 8) * 128 + n) = v;
            }
        }
    }
}

// ======================= launch =======================
extern "C" void kernel_launch(void* const* d_in, const int* in_sizes, int n_in,
                              void* d_out, int out_size) {
    const float* x  = (const float*)d_in[0];
    const float* Ws = (const float*)d_in[1];
    const float* bs = (const float*)d_in[2];
    const float* Wp = (const float*)d_in[3];
    const float* bp = (const float*)d_in[4];
    float* out = (float*)d_out;

    prep_w_kernel<<<4096, 128>>>(Wp);
    encode_kernel<<<dim3(SPAD / 8, BATCH), 128>>>(x, Ws, bs);

    cudaFuncSetAttribute(gemm_kernel, cudaFuncAttributeMaxDynamicSharedMemorySize, SMEM_BYTES);
    gemm_kernel<<<dim3(8, BATCH), 256, SMEM_BYTES>>>(bp, out);

    (void)in_sizes; (void)n_in; (void)out_size;
}

// round 3
// speedup vs baseline: 1.7361x; 1.7361x over previous
#include <cuda_runtime.h>
#include <cuda_fp16.h>
#include <cstdint>
#include <cstddef>

#define BATCH   32
#define NVARS   16
#define SAMPLES 4096
#define EMB     128
#define SPAD    4128      // padded sample rows (max needed s = 4123)
#define NTOK    1016
#define NHW     64        // half-window K-chunks: w2 = w*2+half, K=64 each

// Scratch (device globals: allocation-free rule)
__device__ __align__(1024) __half g_enc[(size_t)BATCH * SPAD * EMB];   // ~33.8 MB
__device__ __align__(1024) __half g_wt[2ull * 128 * 4096];             // Wt[pass][n][k], 2 MB

// ======================= helpers =======================
__device__ __forceinline__ uint32_t smem_u32(const void* p) {
    uint32_t a;
    asm("{ .reg .u64 t; cvta.to.shared.u64 t, %1; cvt.u32.u64 %0, t; }" : "=r"(a) : "l"(p));
    return a;
}
#define CP16(dst, src) \
    asm volatile("cp.async.cg.shared.global [%0], [%1], 16;" :: "r"(dst), "l"(src))
#define CP_COMMIT()  asm volatile("cp.async.commit_group;" ::: "memory")
#define CP_WAIT(n)   asm volatile("cp.async.wait_group %0;" :: "n"(n) : "memory")

#define LDSM4(r, addr) \
    asm volatile("ldmatrix.sync.aligned.m8n8.x4.shared.b16 {%0,%1,%2,%3}, [%4];" \
        : "=r"((r)[0]), "=r"((r)[1]), "=r"((r)[2]), "=r"((r)[3]) : "r"(addr))

#define MMA16816(d, a, b0, b1) \
    asm volatile("mma.sync.aligned.m16n8k16.row.col.f32.f16.f16.f32 " \
        "{%0,%1,%2,%3}, {%4,%5,%6,%7}, {%8,%9}, {%0,%1,%2,%3};" \
        : "+f"((d)[0]), "+f"((d)[1]), "+f"((d)[2]), "+f"((d)[3]) \
        : "r"((a)[0]), "r"((a)[1]), "r"((a)[2]), "r"((a)[3]), "r"(b0), "r"(b1))

// ======================= Kernel 1: split+transpose W_patch (smem transpose) =======================
// Wt[pass][n][k]: pass 0 = fp16(W), pass 1 = fp16(W - hi). 32 blocks, each a 128k x 128n tile.
__global__ void prep_w_kernel(const float* __restrict__ Wp) {
    __shared__ __half tp[128][129];
    int k0 = blockIdx.x * 128;
    int tid = threadIdx.x;  // 256

    // ---- phase 1: hi ----
#pragma unroll
    for (int i = 0; i < 64; i++) {
        int idx = tid + i * 256;            // 16384 elems
        int kr = idx >> 7, n = idx & 127;
        tp[n][kr] = __float2half_rn(Wp[(size_t)(k0 + kr) * 128 + n]);
    }
    __syncthreads();
#pragma unroll
    for (int i = 0; i < 64; i++) {
        int idx = tid + i * 256;
        int n = idx >> 7, kr = idx & 127;
        g_wt[(size_t)n * 4096 + k0 + kr] = tp[n][kr];
    }
    __syncthreads();
    // ---- phase 2: lo ----
#pragma unroll
    for (int i = 0; i < 64; i++) {
        int idx = tid + i * 256;
        int kr = idx >> 7, n = idx & 127;
        float w = Wp[(size_t)(k0 + kr) * 128 + n];
        tp[n][kr] = __float2half_rn(w - __half2float(__float2half_rn(w)));
    }
    __syncthreads();
#pragma unroll
    for (int i = 0; i < 64; i++) {
        int idx = tid + i * 256;
        int n = idx >> 7, kr = idx & 127;
        g_wt[524288 + (size_t)n * 4096 + k0 + kr] = tp[n][kr];
    }
}

// ======================= Kernel 2: encode (stage-1 LSH) =======================
__global__ void encode_kernel(const float* __restrict__ x,
                              const float* __restrict__ Ws,
                              const float* __restrict__ bs) {
    int b = blockIdx.y;
    int s0 = blockIdx.x * 8;
    int tid = threadIdx.x;   // 128; tid == embed dim d
    __shared__ float xs[NVARS][8];
    {
        int v = tid >> 3, s = tid & 7;
        int sg = s0 + s;
        xs[v][s] = (sg < SAMPLES) ? x[((size_t)b * NVARS + v) * SAMPLES + sg] : 0.f;
    }
    __syncthreads();
    float wv[NVARS];
#pragma unroll
    for (int v = 0; v < NVARS; v++) wv[v] = Ws[v * EMB + tid];
    float bias = bs[tid];
#pragma unroll
    for (int s = 0; s < 8; s++) {
        int sg = s0 + s;
        float acc = bias;
#pragma unroll
        for (int v = 0; v < NVARS; v++) acc += xs[v][s] * wv[v];
        float val = (sg < SAMPLES) ? floorf(acc) : 0.f;
        g_enc[((size_t)b * SPAD + sg) * EMB + tid] = __float2half_rn(val);
    }
}

// ======================= Kernel 3: windowed GEMM =======================
// 64 half-window iterations; each stage: A(128x64) + Bhi(128x64) + Blo(128x64), 48KB.
// One A fragment feeds both hi and lo MMAs (same fp32 accumulator).
// Tile rows = 128B = 8 x 16B chunks, XOR swizzle chunk' = c ^ (row&7).
#define STAGE_BYTES 49152u
#define SM_A(buf)  (1024u + (buf) * STAGE_BYTES)
#define SM_BH(buf) (1024u + (buf) * STAGE_BYTES + 16384u)
#define SM_BL(buf) (1024u + (buf) * STAGE_BYTES + 32768u)
#define SMEM_BYTES (1024 + 2 * 49152)

__global__ void __launch_bounds__(256, 2)
gemm_kernel(const float* __restrict__ bp, float* __restrict__ out) {
    extern __shared__ char smem[];
    uint32_t sb = smem_u32(smem);
    int tid = threadIdx.x, wid = tid >> 5, lid = tid & 31;
    int t0 = blockIdx.x * 128;
    int b  = blockIdx.y;

    if (tid < 128) ((float*)(smem + 512))[tid] = bp[tid];

    float acc[2][8][4];
#pragma unroll
    for (int i = 0; i < 2; i++)
#pragma unroll
        for (int j = 0; j < 8; j++)
#pragma unroll
            for (int k = 0; k < 4; k++) acc[i][j][k] = 0.f;

    // base enc offset for this CTA (halfs): row m adds m*512
    const __half* aCta = g_enc + ((size_t)b * SPAD + (size_t)t0 * 4) * EMB;

    // ---- producer: fill one 48KB stage ----
    auto fill = [&](int w2, int buf) {
        int w = w2 >> 1, half = w2 & 1;
        const __half* aSrc = aCta + (size_t)w * EMB + half * 64;
        const __half* bSrc = g_wt + (size_t)w2 * 64;
#pragma unroll
        for (int r = 0; r < 4; r++) {
            int g = tid + r * 256;           // 0..1023
            int row = g >> 3, c = g & 7;
            uint32_t off = (uint32_t)row * 128 + (uint32_t)((c ^ (row & 7)) << 4);
            CP16(sb + SM_A(buf)  + off, (const void*)(aSrc + (size_t)row * 512 + c * 8));
            CP16(sb + SM_BH(buf) + off, (const void*)(bSrc + (size_t)row * 4096 + c * 8));
            CP16(sb + SM_BL(buf) + off, (const void*)(bSrc + 524288 + (size_t)row * 4096 + c * 8));
        }
        CP_COMMIT();
    };

    // ---- consumer addressing (warp tile 32m x 64n; warp grid 4x2) ----
    int wr = wid & 3, wc = wid >> 2;
    uint32_t xorv = (uint32_t)(lid & 7);
    uint32_t aRowOff[2], bRowOff[4];
#pragma unroll
    for (int t = 0; t < 2; t++)
        aRowOff[t] = (uint32_t)(wr * 32 + t * 16 + (lid & 15)) * 128;
#pragma unroll
    for (int p = 0; p < 4; p++)
        bRowOff[p] = (uint32_t)(wc * 64 + p * 16 + (lid & 7) + ((lid & 16) ? 8 : 0)) * 128;
    uint32_t cbA = (uint32_t)(lid >> 4);        // k-half select for A ldmatrix
    uint32_t cbB = (uint32_t)((lid >> 3) & 1);  // k-half select for B ldmatrix

    auto compute = [&](int buf) {
        uint32_t baseA = sb + SM_A(buf), baseBH = sb + SM_BH(buf), baseBL = sb + SM_BL(buf);
#pragma unroll
        for (int kk = 0; kk < 4; kk++) {
            uint32_t aSw = ((2u * kk + cbA) ^ xorv) << 4;
            uint32_t bSw = ((2u * kk + cbB) ^ xorv) << 4;
            uint32_t afr[2][4];
#pragma unroll
            for (int mi = 0; mi < 2; mi++)
                LDSM4(afr[mi], baseA + aRowOff[mi] + aSw);
            uint32_t bfr[4][4];
#pragma unroll
            for (int p = 0; p < 4; p++)
                LDSM4(bfr[p], baseBH + bRowOff[p] + bSw);
#pragma unroll
            for (int mi = 0; mi < 2; mi++)
#pragma unroll
                for (int p = 0; p < 4; p++) {
                    MMA16816(acc[mi][2 * p],     afr[mi], bfr[p][0], bfr[p][1]);
                    MMA16816(acc[mi][2 * p + 1], afr[mi], bfr[p][2], bfr[p][3]);
                }
#pragma unroll
            for (int p = 0; p < 4; p++)
                LDSM4(bfr[p], baseBL + bRowOff[p] + bSw);
#pragma unroll
            for (int mi = 0; mi < 2; mi++)
#pragma unroll
                for (int p = 0; p < 4; p++) {
                    MMA16816(acc[mi][2 * p],     afr[mi], bfr[p][0], bfr[p][1]);
                    MMA16816(acc[mi][2 * p + 1], afr[mi], bfr[p][2], bfr[p][3]);
                }
        }
    };

    // ---- double-buffered main loop ----
    fill(0, 0);
    for (int it = 0; it < NHW; it++) {
        int buf = it & 1;
        if (it + 1 < NHW) {
            fill(it + 1, buf ^ 1);
            CP_WAIT(1);            // stage(it) complete
        } else {
            CP_WAIT(0);
        }
        __syncthreads();
        compute(buf);
        __syncthreads();           // guard stage reuse
    }

    // ---- epilogue: D + b_patch, floor, fp32 stores ----
    const float* bsm = (const float*)(smem + 512);
    int rbase = wr * 32 + (lid >> 2);
    int nb = wc * 64 + (lid & 3) * 2;
#pragma unroll
    for (int mi = 0; mi < 2; mi++) {
        int trow0 = t0 + rbase + mi * 16;
#pragma unroll
        for (int ni = 0; ni < 8; ni++) {
            int n = nb + ni * 8;
            float bx = bsm[n], by = bsm[n + 1];
            if (trow0 < NTOK) {
                float2 v;
                v.x = floorf(acc[mi][ni][0] + bx);
                v.y = floorf(acc[mi][ni][1] + by);
                *(float2*)(out + ((size_t)b * NTOK + trow0) * 128 + n) = v;
            }
            if (trow0 + 8 < NTOK) {
                float2 v;
                v.x = floorf(acc[mi][ni][2] + bx);
                v.y = floorf(acc[mi][ni][3] + by);
                *(float2*)(out + ((size_t)b * NTOK + trow0 + 8) * 128 + n) = v;
            }
        }
    }
}

// ======================= launch =======================
extern "C" void kernel_launch(void* const* d_in, const int* in_sizes, int n_in,
                              void* d_out, int out_size) {
    const float* x  = (const float*)d_in[0];
    const float* Ws = (const float*)d_in[1];
    const float* bs = (const float*)d_in[2];
    const float* Wp = (const float*)d_in[3];
    const float* bp = (const float*)d_in[4];
    float* out = (float*)d_out;

    prep_w_kernel<<<32, 256>>>(Wp);
    encode_kernel<<<dim3(SPAD / 8, BATCH), 128>>>(x, Ws, bs);

    cudaFuncSetAttribute(gemm_kernel, cudaFuncAttributeMaxDynamicSharedMemorySize, SMEM_BYTES);
    gemm_kernel<<<dim3(8, BATCH), 256, SMEM_BYTES>>>(bp, out);

    (void)in_sizes; (void)n_in; (void)out_size;
}

// round 4
// speedup vs baseline: 1.8229x; 1.0500x over previous
#include <cuda_runtime.h>
#include <cuda_fp16.h>
#include <cstdint>
#include <cstddef>

#define BATCH   32
#define NVARS   16
#define SAMPLES 4096
#define EMB     128
#define SPAD    4128      // padded sample rows (max needed s = 4123)
#define NTOK    1016
#define NST     64        // K stages: w2 = w*2 + half, K=64 fp16 each

// Scratch (device globals: allocation-free rule)
__device__ __align__(1024) __half g_enc[(size_t)BATCH * SPAD * EMB];   // ~33.8 MB
__device__ __align__(1024) __half g_wt[2ull * 128 * 4096];             // Wt[pass][n][k], 2 MB

// ======================= helpers =======================
__device__ __forceinline__ uint32_t smem_u32(const void* p) {
    uint32_t a;
    asm("{ .reg .u64 t; cvta.to.shared.u64 t, %1; cvt.u32.u64 %0, t; }" : "=r"(a) : "l"(p));
    return a;
}
#define CP16(dst, src) \
    asm volatile("cp.async.cg.shared.global [%0], [%1], 16;" :: "r"(dst), "l"(src))
#define CP_COMMIT()  asm volatile("cp.async.commit_group;" ::: "memory")
#define CP_WAIT(n)   asm volatile("cp.async.wait_group %0;" :: "n"(n) : "memory")

#define LDSM4(r, addr) \
    asm volatile("ldmatrix.sync.aligned.m8n8.x4.shared.b16 {%0,%1,%2,%3}, [%4];" \
        : "=r"((r)[0]), "=r"((r)[1]), "=r"((r)[2]), "=r"((r)[3]) : "r"(addr))

#define MMA16816(d, a, b0, b1) \
    asm volatile("mma.sync.aligned.m16n8k16.row.col.f32.f16.f16.f32 " \
        "{%0,%1,%2,%3}, {%4,%5,%6,%7}, {%8,%9}, {%0,%1,%2,%3};" \
        : "+f"((d)[0]), "+f"((d)[1]), "+f"((d)[2]), "+f"((d)[3]) \
        : "r"((a)[0]), "r"((a)[1]), "r"((a)[2]), "r"((a)[3]), "r"(b0), "r"(b1))

// ======================= Kernel 1: fused prep_w + encode =======================
// Blocks [0,64):   split+transpose W_patch -> g_wt (64 k-rows x 128 n each)
// Blocks [64,...): encode: enc[b,s,d] = floor(sum_v x*Ws + bs), 16 samples per block
#define PREP_BLOCKS 64
#define ENC_SBLK    258          // SPAD/16

__global__ void __launch_bounds__(256, 3)
prep_encode_kernel(const float* __restrict__ x,
                   const float* __restrict__ Ws,
                   const float* __restrict__ bs,
                   const float* __restrict__ Wp) {
    __shared__ __half tp_h[128][65];
    __shared__ __half tp_l[128][65];
    __shared__ float  xs[NVARS][16];
    int tid = threadIdx.x;
    int bx = blockIdx.x;

    if (bx < PREP_BLOCKS) {
        // ---- W split + transpose: 64 k-rows x 128 n ----
        int k0 = bx * 64;
#pragma unroll 4
        for (int i = 0; i < 32; i++) {
            int idx = tid + i * 256;          // 8192 elems
            int kr = idx >> 7, n = idx & 127;
            float w = Wp[(size_t)(k0 + kr) * 128 + n];
            __half hi = __float2half_rn(w);
            tp_h[n][kr] = hi;
            tp_l[n][kr] = __float2half_rn(w - __half2float(hi));
        }
        __syncthreads();
#pragma unroll 4
        for (int i = 0; i < 32; i++) {
            int idx = tid + i * 256;
            int n = idx >> 6, kr = idx & 63;  // coalesced 64-wide writes
            g_wt[(size_t)n * 4096 + k0 + kr]          = tp_h[n][kr];
            g_wt[524288 + (size_t)n * 4096 + k0 + kr] = tp_l[n][kr];
        }
    } else {
        // ---- encode: 16 samples ----
        int idx = bx - PREP_BLOCKS;
        int b = idx / ENC_SBLK;
        int s0 = (idx - b * ENC_SBLK) * 16;
        {
            int v = tid >> 4, s = tid & 15;
            int sg = s0 + s;
            xs[v][s] = (sg < SAMPLES) ? x[((size_t)b * NVARS + v) * SAMPLES + sg] : 0.f;
        }
        __syncthreads();
        int d = tid & 127;
        int sh = (tid >> 7) * 8;
        float wv[NVARS];
#pragma unroll
        for (int v = 0; v < NVARS; v++) wv[v] = Ws[v * EMB + d];
        float bias = bs[d];
#pragma unroll
        for (int s = 0; s < 8; s++) {
            int sg = s0 + sh + s;
            float acc = bias;
#pragma unroll
            for (int v = 0; v < NVARS; v++) acc += xs[v][sh + s] * wv[v];
            float val = (sg < SAMPLES) ? floorf(acc) : 0.f;
            g_enc[((size_t)b * SPAD + sg) * EMB + d] = __float2half_rn(val);
        }
    }
}

// ======================= Kernel 2: windowed GEMM (batch-paired) =======================
// CTA tile: M=256 (128 tokens of batch b + 128 tokens of batch b+16), N=128.
// 64 stages of K=64; stage smem: A 32KB + Bhi 16KB + Blo 16KB = 64KB; 2 stages.
// One B fill + one B ldsm serves MACs of both batches (2x B amortization).
// Rows are 128B (8 x 16B chunks), XOR swizzle chunk' = c ^ (row&7).
#define SM_A  1024u
#define SM_BH 33792u
#define SM_BL 50176u
#define STAGE_STRIDE 65536u
#define SMEM_BYTES (1024 + 2 * 65536)

__global__ void __launch_bounds__(256, 1)
gemm_kernel(const float* __restrict__ bp, float* __restrict__ out) {
    extern __shared__ char smem[];
    uint32_t sb = smem_u32(smem);
    int tid = threadIdx.x, wid = tid >> 5, lid = tid & 31;
    int t0 = blockIdx.x * 128;
    int b  = blockIdx.y;            // pair (b, b+16)

    if (tid < 128) ((float*)(smem + 512))[tid] = bp[tid];

    float acc[4][8][4];
#pragma unroll
    for (int i = 0; i < 4; i++)
#pragma unroll
        for (int j = 0; j < 8; j++)
#pragma unroll
            for (int k = 0; k < 4; k++) acc[i][j][k] = 0.f;

    // ---- producer addressing (precomputed; only w2*64 varies per stage) ----
    int prow = tid >> 3, pc = tid & 7;           // producer row (0..31 per r-step), 16B chunk
    const __half* aLo = g_enc + ((size_t)b * SPAD) * 128 + (size_t)t0 * 512
                        + (size_t)prow * 512 + pc * 8;
    const __half* aHi = aLo + (size_t)16 * SPAD * 128;   // batch b+16
    const __half* bPt = g_wt + (size_t)prow * 4096 + pc * 8;
    uint32_t pdst = (uint32_t)prow * 128 + (uint32_t)((pc ^ (prow & 7)) << 4);

    auto fill = [&](int w2, int buf) {
        uint32_t st = buf * STAGE_STRIDE;
        size_t off = (size_t)w2 * 64;
#pragma unroll
        for (int r = 0; r < 4; r++) {   // A rows 0..127 (batch b)
            CP16(sb + SM_A + st + pdst + r * 4096u, (const void*)(aLo + off + (size_t)r * 16384));
        }
#pragma unroll
        for (int r = 0; r < 4; r++) {   // A rows 128..255 (batch b+16)
            CP16(sb + SM_A + st + 16384u + pdst + r * 4096u, (const void*)(aHi + off + (size_t)r * 16384));
        }
#pragma unroll
        for (int r = 0; r < 4; r++) {   // B hi
            CP16(sb + SM_BH + st + pdst + r * 4096u, (const void*)(bPt + off + (size_t)r * 131072));
        }
#pragma unroll
        for (int r = 0; r < 4; r++) {   // B lo
            CP16(sb + SM_BL + st + pdst + r * 4096u, (const void*)(bPt + 524288 + off + (size_t)r * 131072));
        }
        CP_COMMIT();
    };

    // ---- consumer addressing (warp tile 64m x 64n; warp grid 4x2) ----
    int wr = wid & 3, wc = wid >> 2;
    uint32_t xorv = (uint32_t)(lid & 7);
    uint32_t aRowOff[4], bRowOff[4];
#pragma unroll
    for (int mi = 0; mi < 4; mi++)
        aRowOff[mi] = (uint32_t)(wr * 64 + mi * 16 + (lid & 15)) * 128;
#pragma unroll
    for (int p = 0; p < 4; p++)
        bRowOff[p] = (uint32_t)(wc * 64 + p * 16 + (lid & 7) + ((lid & 16) ? 8 : 0)) * 128;
    uint32_t cbA = (uint32_t)(lid >> 4);
    uint32_t cbB = (uint32_t)((lid >> 3) & 1);

    auto compute = [&](int buf) {
        uint32_t st = buf * STAGE_STRIDE;
        uint32_t baseA = sb + SM_A + st, baseBH = sb + SM_BH + st, baseBL = sb + SM_BL + st;
#pragma unroll
        for (int kk = 0; kk < 4; kk++) {
            uint32_t aSw = ((2u * kk + cbA) ^ xorv) << 4;
            uint32_t bSw = ((2u * kk + cbB) ^ xorv) << 4;
            uint32_t afr[4][4];
#pragma unroll
            for (int mi = 0; mi < 4; mi++)
                LDSM4(afr[mi], baseA + aRowOff[mi] + aSw);
            uint32_t bfr[4][4];
#pragma unroll
            for (int p = 0; p < 4; p++)
                LDSM4(bfr[p], baseBH + bRowOff[p] + bSw);
#pragma unroll
            for (int mi = 0; mi < 4; mi++)
#pragma unroll
                for (int p = 0; p < 4; p++) {
                    MMA16816(acc[mi][2 * p],     afr[mi], bfr[p][0], bfr[p][1]);
                    MMA16816(acc[mi][2 * p + 1], afr[mi], bfr[p][2], bfr[p][3]);
                }
#pragma unroll
            for (int p = 0; p < 4; p++)
                LDSM4(bfr[p], baseBL + bRowOff[p] + bSw);
#pragma unroll
            for (int mi = 0; mi < 4; mi++)
#pragma unroll
                for (int p = 0; p < 4; p++) {
                    MMA16816(acc[mi][2 * p],     afr[mi], bfr[p][0], bfr[p][1]);
                    MMA16816(acc[mi][2 * p + 1], afr[mi], bfr[p][2], bfr[p][3]);
                }
        }
    };

    // ---- double-buffered main loop ----
    fill(0, 0);
    for (int it = 0; it < NST; it++) {
        int buf = it & 1;
        if (it + 1 < NST) {
            fill(it + 1, buf ^ 1);
            CP_WAIT(1);            // stage(it) complete
        } else {
            CP_WAIT(0);
        }
        __syncthreads();
        compute(buf);
        __syncthreads();           // guard buffer reuse
    }

    // ---- epilogue: D + b_patch, floor, fp32 stores ----
    const float* bsm = (const float*)(smem + 512);
    int bOut = b + ((wr >= 2) ? 16 : 0);
    int rloc = (wr & 1) * 64 + (lid >> 2);     // row within the 128-token half
    int nb = wc * 64 + (lid & 3) * 2;
#pragma unroll
    for (int mi = 0; mi < 4; mi++) {
        int trow0 = t0 + rloc + mi * 16;
#pragma unroll
        for (int ni = 0; ni < 8; ni++) {
            int n = nb + ni * 8;
            float bx = bsm[n], by = bsm[n + 1];
            if (trow0 < NTOK) {
                float2 v;
                v.x = floorf(acc[mi][ni][0] + bx);
                v.y = floorf(acc[mi][ni][1] + by);
                *(float2*)(out + ((size_t)bOut * NTOK + trow0) * 128 + n) = v;
            }
            if (trow0 + 8 < NTOK) {
                float2 v;
                v.x = floorf(acc[mi][ni][2] + bx);
                v.y = floorf(acc[mi][ni][3] + by);
                *(float2*)(out + ((size_t)bOut * NTOK + trow0 + 8) * 128 + n) = v;
            }
        }
    }
}

// ======================= launch =======================
extern "C" void kernel_launch(void* const* d_in, const int* in_sizes, int n_in,
                              void* d_out, int out_size) {
    const float* x  = (const float*)d_in[0];
    const float* Ws = (const float*)d_in[1];
    const float* bs = (const float*)d_in[2];
    const float* Wp = (const float*)d_in[3];
    const float* bp = (const float*)d_in[4];
    float* out = (float*)d_out;

    prep_encode_kernel<<<PREP_BLOCKS + ENC_SBLK * BATCH, 256>>>(x, Ws, bs, Wp);

    cudaFuncSetAttribute(gemm_kernel, cudaFuncAttributeMaxDynamicSharedMemorySize, SMEM_BYTES);
    gemm_kernel<<<dim3(8, 16), 256, SMEM_BYTES>>>(bp, out);

    (void)in_sizes; (void)n_in; (void)out_size;
}